// round 11
// baseline (speedup 1.0000x reference)
#include <cuda_runtime.h>
#include <cuda_bf16.h>
#include <cstdint>

#define NN    50000
#define EE    800000
#define IN_F  128
#define OUT_F 64
#define NH    4
#define HO    256   // NH*OUT_F
#define NEG_SLOPE 0.2f
#define BN_EPS 1e-5f

#define BM 128
#define BK 16

// ---------------- scratch (device globals; zero-init at load, self-cleaned) --
__device__ float        g_h     [(size_t)NN * HO];     // node_feats @ W_fc
__device__ float        g_gres  [(size_t)NN * HO];     // node_feats @ gat_res_w
__device__ float        g_y0    [(size_t)NN * OUT_F];  // relu(node@res_w + res_b)
__device__ float        g_ybuf  [(size_t)NN * OUT_F];  // pre-BN y
__device__ float        g_el    [NN * NH];
__device__ float        g_er    [NN * NH];
__device__ int          g_deg   [NN];                  // self-cleaned (by scan)
__device__ int          g_off   [NN];                  // csr offsets
__device__ int          g_cursor[NN];                  // self-cleaned (by agg)
__device__ int          g_esrc  [EE];                  // dst-sorted src indices
__device__ float        g_bnsum [OUT_F];               // self-cleaned
__device__ float        g_bnsq  [OUT_F];               // self-cleaned
__device__ float        g_scale [OUT_F];
__device__ float        g_shift [OUT_F];

// ---------------- packed f32x2 helpers (sm_103a FFMA2 — PTX-only) -----------
__device__ __forceinline__ void ffma2(unsigned long long& c,
                                      unsigned long long a,
                                      unsigned long long b) {
    asm("fma.rn.f32x2 %0, %1, %2, %0;" : "+l"(c) : "l"(a), "l"(b));
}
__device__ __forceinline__ unsigned long long pack2(float x) {
    unsigned long long r;
    asm("mov.b64 %0, {%1, %1};" : "=l"(r) : "f"(x));
    return r;
}

// ---------------- Kernel 1: three GEMMs in one + fused el/er epilogue -------
// Block tile 128 (M) x 128 (N); 256 threads; 8x8 per-thread microtile.
//   thread (tx,ty): rows ty*8..+7, cols tx*8..+7   (tx=t&15, ty=t>>4)
// acc pairs along M (A-pairs native u64 from k-major As; B packs via mov.b64).
// grid.y = 5: ct 0-1 Wfc (heads 2ct,2ct+1) | ct 2-3 gres | ct 4 res (64 cols)
__global__ void __launch_bounds__(256)
gemm_kernel(const float* __restrict__ A,
            const float* __restrict__ Wfc,
            const float* __restrict__ Wgres,
            const float* __restrict__ Wres,
            const float* __restrict__ res_b,
            const float* __restrict__ attn_l,
            const float* __restrict__ attn_r)
{
    const int ct = blockIdx.y;
    const float* B;
    int ldb, colbase, mode;
    if (ct < 2)      { B = Wfc;   ldb = HO;    colbase = ct * 128;       mode = 0; }
    else if (ct < 4) { B = Wgres; ldb = HO;    colbase = (ct - 2) * 128; mode = 1; }
    else             { B = Wres;  ldb = OUT_F; colbase = 0;              mode = 2; }

    __shared__ float As[BK][BM + 4];    // [k][m], 528B rows (16B aligned)
    __shared__ float Bs[BK][128 + 4];   // [k][n]

    const int t    = threadIdx.x;
    const int lane = t & 31;
    const int tx   = t & 15;
    const int ty   = t >> 4;
    const int row0 = blockIdx.x * BM;
    const int c0   = tx * 8;            // block-local col base

    // A load mapping: row = t&127, kq = (t>>7)*8
    const int ar  = t & 127;
    const int akq = (t >> 7) * 8;
    // B load mapping: kr = t>>4 (0..15), cq = (t&15)*8
    const int bkr = t >> 4;
    const int bcq = (t & 15) * 8;
    const bool bvalid = (mode != 2) || (bcq < OUT_F);

    // acc[rp][j]: u64 = rows (ty*8+2rp, ty*8+2rp+1), col c0+j
    unsigned long long acc[4][8];
#pragma unroll
    for (int rp = 0; rp < 4; rp++)
#pragma unroll
        for (int j = 0; j < 8; j++) acc[rp][j] = 0ull;

    float4 av0, av1, bv0, bv1;
    {   // prefetch tile 0
        int grow = row0 + ar;
        if (grow < NN) {
            const float4* ap = reinterpret_cast<const float4*>(A + (size_t)grow * IN_F + akq);
            av0 = ap[0]; av1 = ap[1];
        } else { av0 = make_float4(0.f,0.f,0.f,0.f); av1 = av0; }
        if (bvalid) {
            const float4* bp = reinterpret_cast<const float4*>(B + (size_t)bkr * ldb + colbase + bcq);
            bv0 = bp[0]; bv1 = bp[1];
        } else { bv0 = make_float4(0.f,0.f,0.f,0.f); bv1 = bv0; }
    }

    for (int kt = 0; kt < IN_F / BK; kt++) {
        As[akq + 0][ar] = av0.x; As[akq + 1][ar] = av0.y;
        As[akq + 2][ar] = av0.z; As[akq + 3][ar] = av0.w;
        As[akq + 4][ar] = av1.x; As[akq + 5][ar] = av1.y;
        As[akq + 6][ar] = av1.z; As[akq + 7][ar] = av1.w;
        *reinterpret_cast<float4*>(&Bs[bkr][bcq])     = bv0;
        *reinterpret_cast<float4*>(&Bs[bkr][bcq + 4]) = bv1;
        __syncthreads();

        if (kt + 1 < IN_F / BK) {     // prefetch next
            int k0 = (kt + 1) * BK;
            int grow = row0 + ar;
            if (grow < NN) {
                const float4* ap = reinterpret_cast<const float4*>(A + (size_t)grow * IN_F + k0 + akq);
                av0 = ap[0]; av1 = ap[1];
            } else { av0 = make_float4(0.f,0.f,0.f,0.f); av1 = av0; }
            if (bvalid)
            {
                const float4* bp = reinterpret_cast<const float4*>(B + (size_t)(k0 + bkr) * ldb + colbase + bcq);
                bv0 = bp[0]; bv1 = bp[1];
            }
        }

#pragma unroll
        for (int kk = 0; kk < BK; kk++) {
            // A: 8 rows = 2x LDS.128, natural M-pairs
            ulonglong2 aLo = *reinterpret_cast<const ulonglong2*>(&As[kk][ty * 8]);      // {r0r1,r2r3}
            ulonglong2 aHi = *reinterpret_cast<const ulonglong2*>(&As[kk][ty * 8 + 4]);  // {r4r5,r6r7}
            // B: 8 cols = 2x LDS.128, pack to {b,b}
            float4 b0 = *reinterpret_cast<const float4*>(&Bs[kk][c0]);
            float4 b1 = *reinterpret_cast<const float4*>(&Bs[kk][c0 + 4]);
            unsigned long long b2[8];
            b2[0] = pack2(b0.x); b2[1] = pack2(b0.y); b2[2] = pack2(b0.z); b2[3] = pack2(b0.w);
            b2[4] = pack2(b1.x); b2[5] = pack2(b1.y); b2[6] = pack2(b1.z); b2[7] = pack2(b1.w);
#pragma unroll
            for (int j = 0; j < 8; j++) {
                ffma2(acc[0][j], aLo.x, b2[j]);
                ffma2(acc[1][j], aLo.y, b2[j]);
                ffma2(acc[2][j], aHi.x, b2[j]);
                ffma2(acc[3][j], aHi.y, b2[j]);
            }
        }
        __syncthreads();
    }

    // ---------------- store outputs ------------------------------------------
    const bool cstore = (mode != 2) || (c0 < OUT_F);
    if (cstore) {
#pragma unroll
        for (int rp = 0; rp < 4; rp++) {
#pragma unroll
            for (int half = 0; half < 2; half++) {
                int grow = row0 + ty * 8 + 2 * rp + half;
                if (grow >= NN) continue;
                float4 v0, v1;
                {
                    const float2* f = reinterpret_cast<const float2*>(acc[rp]);
                    if (half == 0) {
                        v0 = make_float4(f[0].x, f[1].x, f[2].x, f[3].x);
                        v1 = make_float4(f[4].x, f[5].x, f[6].x, f[7].x);
                    } else {
                        v0 = make_float4(f[0].y, f[1].y, f[2].y, f[3].y);
                        v1 = make_float4(f[4].y, f[5].y, f[6].y, f[7].y);
                    }
                }
                int gcol = colbase + c0;
                if (mode == 0) {
                    *reinterpret_cast<float4*>(g_h + (size_t)grow * HO + gcol)     = v0;
                    *reinterpret_cast<float4*>(g_h + (size_t)grow * HO + gcol + 4) = v1;
                } else if (mode == 1) {
                    *reinterpret_cast<float4*>(g_gres + (size_t)grow * HO + gcol)     = v0;
                    *reinterpret_cast<float4*>(g_gres + (size_t)grow * HO + gcol + 4) = v1;
                } else {
                    const float4 rb0 = *reinterpret_cast<const float4*>(res_b + gcol);
                    const float4 rb1 = *reinterpret_cast<const float4*>(res_b + gcol + 4);
                    v0.x = fmaxf(v0.x + rb0.x, 0.f); v0.y = fmaxf(v0.y + rb0.y, 0.f);
                    v0.z = fmaxf(v0.z + rb0.z, 0.f); v0.w = fmaxf(v0.w + rb0.w, 0.f);
                    v1.x = fmaxf(v1.x + rb1.x, 0.f); v1.y = fmaxf(v1.y + rb1.y, 0.f);
                    v1.z = fmaxf(v1.z + rb1.z, 0.f); v1.w = fmaxf(v1.w + rb1.w, 0.f);
                    *reinterpret_cast<float4*>(g_y0 + (size_t)grow * OUT_F + gcol)     = v0;
                    *reinterpret_cast<float4*>(g_y0 + (size_t)grow * OUT_F + gcol + 4) = v1;
                }
            }
        }
    }

    // ---------------- fused el/er epilogue (mode 0) --------------------------
    // col tile = 128 = heads {2ct, 2ct+1}; thread's 8 cols lie in ONE head.
    // Butterfly over lane bits 0-2 stays within same ty (lanes 0-15 / 16-31).
    if (mode == 0) {
        const int head = ct * 2 + (tx >> 3);
        const int hc   = (tx & 7) * 8;          // head-local col base
        unsigned long long al2[8], ar2[8];
        {
            float4 a0 = *reinterpret_cast<const float4*>(attn_l + head * OUT_F + hc);
            float4 a1 = *reinterpret_cast<const float4*>(attn_l + head * OUT_F + hc + 4);
            al2[0]=pack2(a0.x); al2[1]=pack2(a0.y); al2[2]=pack2(a0.z); al2[3]=pack2(a0.w);
            al2[4]=pack2(a1.x); al2[5]=pack2(a1.y); al2[6]=pack2(a1.z); al2[7]=pack2(a1.w);
            float4 r0 = *reinterpret_cast<const float4*>(attn_r + head * OUT_F + hc);
            float4 r1 = *reinterpret_cast<const float4*>(attn_r + head * OUT_F + hc + 4);
            ar2[0]=pack2(r0.x); ar2[1]=pack2(r0.y); ar2[2]=pack2(r0.z); ar2[3]=pack2(r0.w);
            ar2[4]=pack2(r1.x); ar2[5]=pack2(r1.y); ar2[6]=pack2(r1.z); ar2[7]=pack2(r1.w);
        }
#pragma unroll
        for (int rp = 0; rp < 4; rp++) {
            unsigned long long el2 = 0ull, er2 = 0ull;
#pragma unroll
            for (int j = 0; j < 8; j++) {
                ffma2(el2, acc[rp][j], al2[j]);
                ffma2(er2, acc[rp][j], ar2[j]);
            }
            float2 el = *reinterpret_cast<float2*>(&el2);
            float2 er = *reinterpret_cast<float2*>(&er2);
#pragma unroll
            for (int d = 1; d < 8; d <<= 1) {
                el.x += __shfl_xor_sync(0xffffffffu, el.x, d);
                el.y += __shfl_xor_sync(0xffffffffu, el.y, d);
                er.x += __shfl_xor_sync(0xffffffffu, er.x, d);
                er.y += __shfl_xor_sync(0xffffffffu, er.y, d);
            }
            if ((tx & 7) == 0) {
                int grow = row0 + ty * 8 + 2 * rp;
                if (grow < NN)     { g_el[grow * NH + head] = el.x;       g_er[grow * NH + head] = er.x; }
                if (grow + 1 < NN) { g_el[(grow + 1) * NH + head] = el.y; g_er[(grow + 1) * NH + head] = er.y; }
            }
        }
    }
}

// ---------------- Kernel 3a: degree histogram --------------------------------
__global__ void hist_kernel(const int* __restrict__ dst)
{
    int e = blockIdx.x * blockDim.x + threadIdx.x;
    if (e >= EE) return;
    atomicAdd(&g_deg[dst[e]], 1);
}

// ---------------- Kernel 3b: exclusive scan (1 block) + zero g_deg ----------
__global__ void scan_kernel()
{
    const int tid = threadIdx.x;   // 1024 threads
    __shared__ int wsum[32];
    __shared__ int s_carry;
    if (tid == 0) s_carry = 0;
    __syncthreads();
    for (int base = 0; base < NN; base += 1024) {
        int i = base + tid;
        int v = (i < NN) ? g_deg[i] : 0;
        if (i < NN) g_deg[i] = 0;            // self-clean
        int incl = v;
#pragma unroll
        for (int o = 1; o < 32; o <<= 1) {
            int t = __shfl_up_sync(0xffffffffu, incl, o);
            if ((tid & 31) >= o) incl += t;
        }
        if ((tid & 31) == 31) wsum[tid >> 5] = incl;
        __syncthreads();
        if (tid < 32) {
            int w = wsum[tid];
            int wi = w;
#pragma unroll
            for (int o = 1; o < 32; o <<= 1) {
                int t = __shfl_up_sync(0xffffffffu, wi, o);
                if (tid >= o) wi += t;
            }
            wsum[tid] = wi - w;              // exclusive warp offset
        }
        __syncthreads();
        incl += wsum[tid >> 5];
        int carry = s_carry;
        if (i < NN) g_off[i] = carry + incl - v;
        __syncthreads();                      // all reads of s_carry done
        if (tid == 1023) s_carry = carry + incl;
        __syncthreads();
    }
}

// ---------------- Kernel 3c: scatter src into dst-sorted order ---------------
__global__ void scatter_kernel(const int* __restrict__ src,
                               const int* __restrict__ dst)
{
    int e = blockIdx.x * blockDim.x + threadIdx.x;
    if (e >= EE) return;
    int d = dst[e];
    int p = g_off[d] + atomicAdd(&g_cursor[d], 1);
    g_esrc[p] = src[e];
}

// ---------------- Kernel 4: fused per-dst softmax + aggregation + epilogue --
// warp per dst node; 8 warps/block; grid = NN/8 (exact: 50000 = 6250*8)
__global__ void agg_kernel(const float* __restrict__ gat_bias,
                           const float* __restrict__ conv_w,
                           const float* __restrict__ conv_b)
{
    const int lane = threadIdx.x & 31;
    const int w    = threadIdx.x >> 5;      // 0..7
    const int n    = blockIdx.x * 8 + w;

    const int off = g_off[n];
    const int deg = g_cursor[n];

    const float4 er4 = *reinterpret_cast<const float4*>(g_er + n * 4);

    // pass 1: per-head max over incoming edges
    float m0 = -1e30f, m1 = -1e30f, m2 = -1e30f, m3 = -1e30f;
    for (int base = 0; base < deg; base += 32) {
        int e = base + lane;
        int s = (e < deg) ? g_esrc[off + e] : 0;
        float4 elv = *reinterpret_cast<const float4*>(g_el + s * 4);
        float l0 = elv.x + er4.x; l0 = (l0 >= 0.f) ? l0 : NEG_SLOPE * l0;
        float l1 = elv.y + er4.y; l1 = (l1 >= 0.f) ? l1 : NEG_SLOPE * l1;
        float l2 = elv.z + er4.z; l2 = (l2 >= 0.f) ? l2 : NEG_SLOPE * l2;
        float l3 = elv.w + er4.w; l3 = (l3 >= 0.f) ? l3 : NEG_SLOPE * l3;
        if (e < deg) {
            m0 = fmaxf(m0, l0); m1 = fmaxf(m1, l1);
            m2 = fmaxf(m2, l2); m3 = fmaxf(m3, l3);
        }
    }
#pragma unroll
    for (int o = 16; o; o >>= 1) {
        m0 = fmaxf(m0, __shfl_xor_sync(0xffffffffu, m0, o));
        m1 = fmaxf(m1, __shfl_xor_sync(0xffffffffu, m1, o));
        m2 = fmaxf(m2, __shfl_xor_sync(0xffffffffu, m2, o));
        m3 = fmaxf(m3, __shfl_xor_sync(0xffffffffu, m3, o));
    }

    // pass 2: exp, segment sum, weighted aggregation (in registers)
    float s0 = 0.f, s1 = 0.f, s2 = 0.f, s3 = 0.f;
    float4 acc0 = make_float4(0.f, 0.f, 0.f, 0.f);
    float4 acc1 = make_float4(0.f, 0.f, 0.f, 0.f);
    for (int base = 0; base < deg; base += 32) {
        int cnt = min(32, deg - base);
        int e = base + lane;
        int sidx = (e < deg) ? g_esrc[off + e] : 0;
        float4 elv = *reinterpret_cast<const float4*>(g_el + sidx * 4);
        float l0 = elv.x + er4.x; l0 = (l0 >= 0.f) ? l0 : NEG_SLOPE * l0;
        float l1 = elv.y + er4.y; l1 = (l1 >= 0.f) ? l1 : NEG_SLOPE * l1;
        float l2 = elv.z + er4.z; l2 = (l2 >= 0.f) ? l2 : NEG_SLOPE * l2;
        float l3 = elv.w + er4.w; l3 = (l3 >= 0.f) ? l3 : NEG_SLOPE * l3;
        float a0 = (e < deg) ? __expf(l0 - m0) : 0.f;
        float a1 = (e < deg) ? __expf(l1 - m1) : 0.f;
        float a2 = (e < deg) ? __expf(l2 - m2) : 0.f;
        float a3 = (e < deg) ? __expf(l3 - m3) : 0.f;
        s0 += a0; s1 += a1; s2 += a2; s3 += a3;

        for (int ee = 0; ee < cnt; ee++) {
            int   sv = __shfl_sync(0xffffffffu, sidx, ee);
            float b0 = __shfl_sync(0xffffffffu, a0, ee);
            float b1 = __shfl_sync(0xffffffffu, a1, ee);
            float b2 = __shfl_sync(0xffffffffu, a2, ee);
            float b3 = __shfl_sync(0xffffffffu, a3, ee);
            float w0 = (lane < 16) ? b0 : b1;
            float w1 = (lane < 16) ? b2 : b3;
            const float4* hrow = reinterpret_cast<const float4*>(g_h + (size_t)sv * HO);
            float4 h0 = hrow[lane];
            float4 h1 = hrow[lane + 32];
            acc0.x = fmaf(w0, h0.x, acc0.x); acc0.y = fmaf(w0, h0.y, acc0.y);
            acc0.z = fmaf(w0, h0.z, acc0.z); acc0.w = fmaf(w0, h0.w, acc0.w);
            acc1.x = fmaf(w1, h1.x, acc1.x); acc1.y = fmaf(w1, h1.y, acc1.y);
            acc1.z = fmaf(w1, h1.z, acc1.z); acc1.w = fmaf(w1, h1.w, acc1.w);
        }
    }
#pragma unroll
    for (int o = 16; o; o >>= 1) {
        s0 += __shfl_xor_sync(0xffffffffu, s0, o);
        s1 += __shfl_xor_sync(0xffffffffu, s1, o);
        s2 += __shfl_xor_sync(0xffffffffu, s2, o);
        s3 += __shfl_xor_sync(0xffffffffu, s3, o);
    }

    // normalize + gat residual + bias + relu + conv head-merge
    const float invA = 1.f / (((lane < 16) ? s0 : s1) + 1e-16f);
    const float invB = 1.f / (((lane < 16) ? s2 : s3) + 1e-16f);
    const int hA = (lane < 16) ? 0 : 1;
    const int hB = (lane < 16) ? 2 : 3;
    const int c4 = (lane & 15) * 4;
    const float4 gA = *reinterpret_cast<const float4*>(g_gres + (size_t)n * HO + hA * OUT_F + c4);
    const float4 gB = *reinterpret_cast<const float4*>(g_gres + (size_t)n * HO + hB * OUT_F + c4);
    const float4 bA = *reinterpret_cast<const float4*>(gat_bias + hA * OUT_F + c4);
    const float4 bB = *reinterpret_cast<const float4*>(gat_bias + hB * OUT_F + c4);
    const float cwA = conv_w[hA], cwB = conv_w[hB];

    float4 part;
    part.x = fmaxf(acc0.x * invA + gA.x + bA.x, 0.f) * cwA + fmaxf(acc1.x * invB + gB.x + bB.x, 0.f) * cwB;
    part.y = fmaxf(acc0.y * invA + gA.y + bA.y, 0.f) * cwA + fmaxf(acc1.y * invB + gB.y + bB.y, 0.f) * cwB;
    part.z = fmaxf(acc0.z * invA + gA.z + bA.z, 0.f) * cwA + fmaxf(acc1.z * invB + gB.z + bB.z, 0.f) * cwB;
    part.w = fmaxf(acc0.w * invA + gA.w + bA.w, 0.f) * cwA + fmaxf(acc1.w * invB + gB.w + bB.w, 0.f) * cwB;
    part.x += __shfl_xor_sync(0xffffffffu, part.x, 16);
    part.y += __shfl_xor_sync(0xffffffffu, part.y, 16);
    part.z += __shfl_xor_sync(0xffffffffu, part.z, 16);
    part.w += __shfl_xor_sync(0xffffffffu, part.w, 16);

    __shared__ float shs[8][68];
    __shared__ float shq[8][68];
    if (lane < 16) {
        const float4 y0v = *reinterpret_cast<const float4*>(g_y0 + (size_t)n * OUT_F + c4);
        const float cb = conv_b[0];
        float4 y4;
        y4.x = part.x + cb + y0v.x;
        y4.y = part.y + cb + y0v.y;
        y4.z = part.z + cb + y0v.z;
        y4.w = part.w + cb + y0v.w;
        *reinterpret_cast<float4*>(g_ybuf + (size_t)n * OUT_F + c4) = y4;
        *reinterpret_cast<float4*>(&shs[w][c4]) = y4;
        float4 q = make_float4(y4.x * y4.x, y4.y * y4.y, y4.z * y4.z, y4.w * y4.w);
        *reinterpret_cast<float4*>(&shq[w][c4]) = q;
    }
    if (lane == 0) g_cursor[n] = 0;          // self-clean for next launch
    __syncthreads();

    const int t = threadIdx.x;
    if (t < 64) {
        float sv = 0.f;
#pragma unroll
        for (int r = 0; r < 8; r++) sv += shs[r][t];
        atomicAdd(&g_bnsum[t], sv);
    } else if (t >= 128 && t < 192) {
        int d = t - 128;
        float qv = 0.f;
#pragma unroll
        for (int r = 0; r < 8; r++) qv += shq[r][d];
        atomicAdd(&g_bnsq[d], qv);
    }
}

// ---------------- Kernel 5: BN stats -> scale/shift (+ self-clean) ----------
__global__ void bn_stats_kernel(const float* __restrict__ gamma,
                                const float* __restrict__ beta)
{
    int d = threadIdx.x;
    if (d >= OUT_F) return;
    float mean = g_bnsum[d] / (float)NN;
    float var  = g_bnsq[d] / (float)NN - mean * mean;
    float rstd = rsqrtf(var + BN_EPS);
    float sc = gamma[d] * rstd;
    g_scale[d] = sc;
    g_shift[d] = beta[d] - mean * sc;
    g_bnsum[d] = 0.f;   // self-clean
    g_bnsq[d]  = 0.f;
}

// ---------------- Kernel 6: normalize -> d_out -------------------------------
__global__ void bn_apply_kernel(float* __restrict__ out)
{
    int i = blockIdx.x * blockDim.x + threadIdx.x;
    if (i >= NN * OUT_F) return;
    int d = i & (OUT_F - 1);
    out[i] = g_ybuf[i] * g_scale[d] + g_shift[d];
}

// ---------------- launch -----------------------------------------------------
extern "C" void kernel_launch(void* const* d_in, const int* in_sizes, int n_in,
                              void* d_out, int out_size)
{
    const float* node_feats = (const float*)d_in[0];
    const float* W_fc       = (const float*)d_in[1];
    const float* attn_l     = (const float*)d_in[2];
    const float* attn_r     = (const float*)d_in[3];
    const float* gat_res_w  = (const float*)d_in[4];
    const float* gat_bias   = (const float*)d_in[5];
    const float* conv_w     = (const float*)d_in[6];
    const float* conv_b     = (const float*)d_in[7];
    const float* res_w      = (const float*)d_in[8];
    const float* res_b      = (const float*)d_in[9];
    const float* bn_gamma   = (const float*)d_in[10];
    const float* bn_beta    = (const float*)d_in[11];
    const int*   src        = (const int*)d_in[12];
    const int*   dst        = (const int*)d_in[13];
    float*       out        = (float*)d_out;

    // edge sort (independent of GEMM output)
    hist_kernel<<<(EE + 255) / 256, 256>>>(dst);
    scan_kernel<<<1, 1024>>>();
    scatter_kernel<<<(EE + 255) / 256, 256>>>(src, dst);

    // three GEMMs (+ fused el/er epilogue)
    {
        dim3 grid((NN + BM - 1) / BM, 5);
        gemm_kernel<<<grid, 256>>>(node_feats, W_fc, gat_res_w, res_w, res_b,
                                   attn_l, attn_r);
    }
    // fused softmax + aggregation + node epilogue + BN partials
    agg_kernel<<<NN / 8, 256>>>(gat_bias, conv_w, conv_b);
    // BN stats
    bn_stats_kernel<<<1, 64>>>(bn_gamma, bn_beta);
    // normalize
    bn_apply_kernel<<<(NN * OUT_F + 255) / 256, 256>>>(out);
}

// round 13
// speedup vs baseline: 1.3202x; 1.3202x over previous
#include <cuda_runtime.h>
#include <cuda_bf16.h>
#include <cstdint>

#define NN    50000
#define EE    800000
#define IN_F  128
#define OUT_F 64
#define NH    4
#define HO    256   // NH*OUT_F
#define NEG_SLOPE 0.2f
#define BN_EPS 1e-5f

#define BMT   64    // M tile
#define PITCH 136   // bf16 elems per smem row (272B: conflict-free, 16B-aligned)

// ---------------- scratch (device globals; zero-init at load, self-cleaned) --
__device__ float        g_h     [(size_t)NN * HO];
__device__ float        g_gres  [(size_t)NN * HO];
__device__ float        g_y0    [(size_t)NN * OUT_F];
__device__ float        g_ybuf  [(size_t)NN * OUT_F];
__device__ float        g_el    [NN * NH];
__device__ float        g_er    [NN * NH];
__device__ int          g_deg   [NN];
__device__ int          g_off   [NN];
__device__ int          g_cursor[NN];
__device__ int          g_esrc  [EE];
__device__ float        g_bnsum [OUT_F];
__device__ float        g_bnsq  [OUT_F];
__device__ float        g_scale [OUT_F];
__device__ float        g_shift [OUT_F];

// ---------------- m16n8k16 bf16 MMA (sm_80+ PTX -> HMMA on sm_103) ----------
__device__ __forceinline__ void mma_bf16(float* c, const uint32_t* a,
                                         uint32_t b0, uint32_t b1) {
    asm volatile("mma.sync.aligned.m16n8k16.row.col.f32.bf16.bf16.f32 "
        "{%0,%1,%2,%3}, {%4,%5,%6,%7}, {%8,%9}, {%0,%1,%2,%3};"
        : "+f"(c[0]), "+f"(c[1]), "+f"(c[2]), "+f"(c[3])
        : "r"(a[0]), "r"(a[1]), "r"(a[2]), "r"(a[3]), "r"(b0), "r"(b1));
}

__device__ __forceinline__ void cvt_hilo8(const float* x, uint32_t* hw, uint32_t* lw) {
#pragma unroll
    for (int jp = 0; jp < 4; jp++) {
        __nv_bfloat16 h0 = __float2bfloat16(x[2*jp]);
        __nv_bfloat16 h1 = __float2bfloat16(x[2*jp+1]);
        __nv_bfloat16 l0 = __float2bfloat16(x[2*jp]   - __bfloat162float(h0));
        __nv_bfloat16 l1 = __float2bfloat16(x[2*jp+1] - __bfloat162float(h1));
        hw[jp] = (uint32_t)__bfloat16_as_ushort(h0) | ((uint32_t)__bfloat16_as_ushort(h1) << 16);
        lw[jp] = (uint32_t)__bfloat16_as_ushort(l0) | ((uint32_t)__bfloat16_as_ushort(l1) << 16);
    }
}

// smem layout (bf16 elems): AH | AL | BH | BL, then float ELP[4][64], ERP[4][64]
#define SM_ELEMS (4 * BMT * PITCH)
#define SM_TOTAL (SM_ELEMS * 2 + 2 * 4 * BMT * 4)

// ---------------- Kernel 1: tensor-core GEMM (bf16 hi/lo, 3-pass) ------------
// Block tile 64(M) x 64(N), K=128. 256 threads = 8 warps: w&1 = m-half (32),
// w>>1 = n-quarter (16). Per warp: 2mi x 2nj x 8k m16n8k16 MMAs per pass.
// grid = (ceil(NN/64), 9): ct 0-3 Wfc head ct | 4-7 gres | 8 res
__global__ void __launch_bounds__(256, 2)
gemm_kernel(const float* __restrict__ A,
            const float* __restrict__ Wfc,
            const float* __restrict__ Wgres,
            const float* __restrict__ Wres,
            const float* __restrict__ res_b,
            const float* __restrict__ attn_l,
            const float* __restrict__ attn_r)
{
    extern __shared__ char smem[];
    __nv_bfloat16* AH = reinterpret_cast<__nv_bfloat16*>(smem);
    __nv_bfloat16* AL = AH + BMT * PITCH;
    __nv_bfloat16* BH = AL + BMT * PITCH;
    __nv_bfloat16* BL = BH + BMT * PITCH;
    float* ELP = reinterpret_cast<float*>(BL + BMT * PITCH);   // [4][64]
    float* ERP = ELP + 4 * BMT;

    const int ct = blockIdx.y;
    const float* B;
    int ldb, colbase, mode;
    if (ct < 4)      { B = Wfc;   ldb = HO;    colbase = ct * 64;       mode = 0; }
    else if (ct < 8) { B = Wgres; ldb = HO;    colbase = (ct - 4) * 64; mode = 1; }
    else             { B = Wres;  ldb = OUT_F; colbase = 0;             mode = 2; }

    const int t    = threadIdx.x;
    const int row0 = blockIdx.x * BMT;

    // ---- convert A tile (64 rows x 128 k) fp32 -> bf16 hi/lo ----------------
    for (int i = t; i < BMT * 16; i += 256) {
        int m  = i >> 4;
        int kg = (i & 15) * 8;
        float x[8];
        int grow = row0 + m;
        if (grow < NN) {
            const float4* ap = reinterpret_cast<const float4*>(A + (size_t)grow * IN_F + kg);
            float4 v0 = ap[0], v1 = ap[1];
            x[0]=v0.x; x[1]=v0.y; x[2]=v0.z; x[3]=v0.w;
            x[4]=v1.x; x[5]=v1.y; x[6]=v1.z; x[7]=v1.w;
        } else {
#pragma unroll
            for (int j = 0; j < 8; j++) x[j] = 0.f;
        }
        uint32_t hw[4], lw[4];
        cvt_hilo8(x, hw, lw);
        *reinterpret_cast<uint4*>(AH + m * PITCH + kg) = make_uint4(hw[0], hw[1], hw[2], hw[3]);
        *reinterpret_cast<uint4*>(AL + m * PITCH + kg) = make_uint4(lw[0], lw[1], lw[2], lw[3]);
    }
    // ---- convert B^T tile: W[k][colbase+n] -> Bt[n][k] bf16 hi/lo -----------
    for (int i = t; i < 64 * 16; i += 256) {
        int n  = i & 63;
        int kg = (i >> 6) * 8;
        float x[8];
#pragma unroll
        for (int j = 0; j < 8; j++) x[j] = B[(size_t)(kg + j) * ldb + colbase + n];
        uint32_t hw[4], lw[4];
        cvt_hilo8(x, hw, lw);
        *reinterpret_cast<uint4*>(BH + n * PITCH + kg) = make_uint4(hw[0], hw[1], hw[2], hw[3]);
        *reinterpret_cast<uint4*>(BL + n * PITCH + kg) = make_uint4(lw[0], lw[1], lw[2], lw[3]);
    }
    __syncthreads();

    // ---- warp tiling ---------------------------------------------------------
    const int lane = t & 31;
    const int w    = t >> 5;
    const int m0   = (w & 1) * 32;
    const int n0   = (w >> 1) * 16;
    const int g    = lane >> 2;      // group 0..7
    const int tt   = lane & 3;       // thread-in-group

    float acc[2][2][4];
#pragma unroll
    for (int mi = 0; mi < 2; mi++)
#pragma unroll
        for (int nj = 0; nj < 2; nj++)
#pragma unroll
            for (int q = 0; q < 4; q++) acc[mi][nj][q] = 0.f;

    // 3 passes: AhBh, AhBl, AlBh
#pragma unroll
    for (int pass = 0; pass < 3; pass++) {
        const __nv_bfloat16* Asm = (pass == 2) ? AL : AH;
        const __nv_bfloat16* Bsm = (pass == 1) ? BL : BH;
#pragma unroll
        for (int ks = 0; ks < 8; ks++) {
            const int k0 = ks * 16;
            uint32_t a[2][4];
#pragma unroll
            for (int mi = 0; mi < 2; mi++) {
                const __nv_bfloat16* p = Asm + (m0 + mi * 16 + g) * PITCH + k0 + tt * 2;
                a[mi][0] = *reinterpret_cast<const uint32_t*>(p);
                a[mi][1] = *reinterpret_cast<const uint32_t*>(p + 8 * PITCH);
                a[mi][2] = *reinterpret_cast<const uint32_t*>(p + 8);
                a[mi][3] = *reinterpret_cast<const uint32_t*>(p + 8 * PITCH + 8);
            }
#pragma unroll
            for (int nj = 0; nj < 2; nj++) {
                const __nv_bfloat16* q = Bsm + (n0 + nj * 8 + g) * PITCH + k0 + tt * 2;
                uint32_t b0 = *reinterpret_cast<const uint32_t*>(q);
                uint32_t b1 = *reinterpret_cast<const uint32_t*>(q + 8);
                mma_bf16(acc[0][nj], a[0], b0, b1);
                mma_bf16(acc[1][nj], a[1], b0, b1);
            }
        }
    }

    // ---- store outputs (c-frag: c0 row g col tt*2, c1 col+1, c2/c3 row g+8) --
#pragma unroll
    for (int mi = 0; mi < 2; mi++) {
#pragma unroll
        for (int nj = 0; nj < 2; nj++) {
            int lrow = m0 + mi * 16 + g;
            int col  = colbase + n0 + nj * 8 + tt * 2;
            int r0g  = row0 + lrow;
            int r1g  = r0g + 8;
            float2 v0 = make_float2(acc[mi][nj][0], acc[mi][nj][1]);
            float2 v1 = make_float2(acc[mi][nj][2], acc[mi][nj][3]);
            if (mode == 0) {
                if (r0g < NN) *reinterpret_cast<float2*>(g_h + (size_t)r0g * HO + col) = v0;
                if (r1g < NN) *reinterpret_cast<float2*>(g_h + (size_t)r1g * HO + col) = v1;
            } else if (mode == 1) {
                if (r0g < NN) *reinterpret_cast<float2*>(g_gres + (size_t)r0g * HO + col) = v0;
                if (r1g < NN) *reinterpret_cast<float2*>(g_gres + (size_t)r1g * HO + col) = v1;
            } else {
                float rb0 = res_b[col], rb1 = res_b[col + 1];
                if (r0g < NN)
                    *reinterpret_cast<float2*>(g_y0 + (size_t)r0g * OUT_F + col) =
                        make_float2(fmaxf(v0.x + rb0, 0.f), fmaxf(v0.y + rb1, 0.f));
                if (r1g < NN)
                    *reinterpret_cast<float2*>(g_y0 + (size_t)r1g * OUT_F + col) =
                        make_float2(fmaxf(v1.x + rb0, 0.f), fmaxf(v1.y + rb1, 0.f));
            }
        }
    }

    // ---- fused el/er (mode 0): per-row dot with attn vectors -----------------
    if (mode == 0) {
        const int head = ct;
#pragma unroll
        for (int mi = 0; mi < 2; mi++) {
#pragma unroll
            for (int hh = 0; hh < 2; hh++) {
                int lrow = m0 + mi * 16 + g + hh * 8;
                float el = 0.f, er = 0.f;
#pragma unroll
                for (int nj = 0; nj < 2; nj++) {
                    int col = n0 + nj * 8 + tt * 2;   // head-local
                    float c0 = acc[mi][nj][hh * 2];
                    float c1 = acc[mi][nj][hh * 2 + 1];
                    el += c0 * attn_l[head * OUT_F + col] + c1 * attn_l[head * OUT_F + col + 1];
                    er += c0 * attn_r[head * OUT_F + col] + c1 * attn_r[head * OUT_F + col + 1];
                }
                el += __shfl_xor_sync(0xffffffffu, el, 1);
                el += __shfl_xor_sync(0xffffffffu, el, 2);
                er += __shfl_xor_sync(0xffffffffu, er, 1);
                er += __shfl_xor_sync(0xffffffffu, er, 2);
                if (tt == 0) {
                    ELP[(w >> 1) * BMT + lrow] = el;
                    ERP[(w >> 1) * BMT + lrow] = er;
                }
            }
        }
    }
    __syncthreads();
    if (mode == 0 && t < BMT) {
        int grow = row0 + t;
        if (grow < NN) {
            float el = ELP[t] + ELP[BMT + t] + ELP[2 * BMT + t] + ELP[3 * BMT + t];
            float er = ERP[t] + ERP[BMT + t] + ERP[2 * BMT + t] + ERP[3 * BMT + t];
            g_el[grow * NH + ct] = el;
            g_er[grow * NH + ct] = er;
        }
    }
}

// ---------------- Kernel 3a: degree histogram --------------------------------
__global__ void hist_kernel(const int* __restrict__ dst)
{
    int e = blockIdx.x * blockDim.x + threadIdx.x;
    if (e >= EE) return;
    atomicAdd(&g_deg[dst[e]], 1);
}

// ---------------- Kernel 3b: exclusive scan (1 block) + zero g_deg ----------
__global__ void scan_kernel()
{
    const int tid = threadIdx.x;   // 1024 threads
    __shared__ int wsum[32];
    __shared__ int s_carry;
    if (tid == 0) s_carry = 0;
    __syncthreads();
    for (int base = 0; base < NN; base += 1024) {
        int i = base + tid;
        int v = (i < NN) ? g_deg[i] : 0;
        if (i < NN) g_deg[i] = 0;            // self-clean
        int incl = v;
#pragma unroll
        for (int o = 1; o < 32; o <<= 1) {
            int t = __shfl_up_sync(0xffffffffu, incl, o);
            if ((tid & 31) >= o) incl += t;
        }
        if ((tid & 31) == 31) wsum[tid >> 5] = incl;
        __syncthreads();
        if (tid < 32) {
            int w = wsum[tid];
            int wi = w;
#pragma unroll
            for (int o = 1; o < 32; o <<= 1) {
                int t = __shfl_up_sync(0xffffffffu, wi, o);
                if (tid >= o) wi += t;
            }
            wsum[tid] = wi - w;              // exclusive warp offset
        }
        __syncthreads();
        incl += wsum[tid >> 5];
        int carry = s_carry;
        if (i < NN) g_off[i] = carry + incl - v;
        __syncthreads();
        if (tid == 1023) s_carry = carry + incl;
        __syncthreads();
    }
}

// ---------------- Kernel 3c: scatter src into dst-sorted order ---------------
__global__ void scatter_kernel(const int* __restrict__ src,
                               const int* __restrict__ dst)
{
    int e = blockIdx.x * blockDim.x + threadIdx.x;
    if (e >= EE) return;
    int d = dst[e];
    int p = g_off[d] + atomicAdd(&g_cursor[d], 1);
    g_esrc[p] = src[e];
}

// ---------------- Kernel 4: fused per-dst softmax + aggregation + epilogue --
__global__ void agg_kernel(const float* __restrict__ gat_bias,
                           const float* __restrict__ conv_w,
                           const float* __restrict__ conv_b)
{
    const int lane = threadIdx.x & 31;
    const int w    = threadIdx.x >> 5;      // 0..7
    const int n    = blockIdx.x * 8 + w;

    const int off = g_off[n];
    const int deg = g_cursor[n];

    const float4 er4 = *reinterpret_cast<const float4*>(g_er + n * 4);

    float m0 = -1e30f, m1 = -1e30f, m2 = -1e30f, m3 = -1e30f;
    for (int base = 0; base < deg; base += 32) {
        int e = base + lane;
        int s = (e < deg) ? g_esrc[off + e] : 0;
        float4 elv = *reinterpret_cast<const float4*>(g_el + s * 4);
        float l0 = elv.x + er4.x; l0 = (l0 >= 0.f) ? l0 : NEG_SLOPE * l0;
        float l1 = elv.y + er4.y; l1 = (l1 >= 0.f) ? l1 : NEG_SLOPE * l1;
        float l2 = elv.z + er4.z; l2 = (l2 >= 0.f) ? l2 : NEG_SLOPE * l2;
        float l3 = elv.w + er4.w; l3 = (l3 >= 0.f) ? l3 : NEG_SLOPE * l3;
        if (e < deg) {
            m0 = fmaxf(m0, l0); m1 = fmaxf(m1, l1);
            m2 = fmaxf(m2, l2); m3 = fmaxf(m3, l3);
        }
    }
#pragma unroll
    for (int o = 16; o; o >>= 1) {
        m0 = fmaxf(m0, __shfl_xor_sync(0xffffffffu, m0, o));
        m1 = fmaxf(m1, __shfl_xor_sync(0xffffffffu, m1, o));
        m2 = fmaxf(m2, __shfl_xor_sync(0xffffffffu, m2, o));
        m3 = fmaxf(m3, __shfl_xor_sync(0xffffffffu, m3, o));
    }

    float s0 = 0.f, s1 = 0.f, s2 = 0.f, s3 = 0.f;
    float4 acc0 = make_float4(0.f, 0.f, 0.f, 0.f);
    float4 acc1 = make_float4(0.f, 0.f, 0.f, 0.f);
    for (int base = 0; base < deg; base += 32) {
        int cnt = min(32, deg - base);
        int e = base + lane;
        int sidx = (e < deg) ? g_esrc[off + e] : 0;
        float4 elv = *reinterpret_cast<const float4*>(g_el + sidx * 4);
        float l0 = elv.x + er4.x; l0 = (l0 >= 0.f) ? l0 : NEG_SLOPE * l0;
        float l1 = elv.y + er4.y; l1 = (l1 >= 0.f) ? l1 : NEG_SLOPE * l1;
        float l2 = elv.z + er4.z; l2 = (l2 >= 0.f) ? l2 : NEG_SLOPE * l2;
        float l3 = elv.w + er4.w; l3 = (l3 >= 0.f) ? l3 : NEG_SLOPE * l3;
        float a0 = (e < deg) ? __expf(l0 - m0) : 0.f;
        float a1 = (e < deg) ? __expf(l1 - m1) : 0.f;
        float a2 = (e < deg) ? __expf(l2 - m2) : 0.f;
        float a3 = (e < deg) ? __expf(l3 - m3) : 0.f;
        s0 += a0; s1 += a1; s2 += a2; s3 += a3;

        for (int ee = 0; ee < cnt; ee++) {
            int   sv = __shfl_sync(0xffffffffu, sidx, ee);
            float b0 = __shfl_sync(0xffffffffu, a0, ee);
            float b1 = __shfl_sync(0xffffffffu, a1, ee);
            float b2 = __shfl_sync(0xffffffffu, a2, ee);
            float b3 = __shfl_sync(0xffffffffu, a3, ee);
            float w0 = (lane < 16) ? b0 : b1;
            float w1 = (lane < 16) ? b2 : b3;
            const float4* hrow = reinterpret_cast<const float4*>(g_h + (size_t)sv * HO);
            float4 h0 = hrow[lane];
            float4 h1 = hrow[lane + 32];
            acc0.x = fmaf(w0, h0.x, acc0.x); acc0.y = fmaf(w0, h0.y, acc0.y);
            acc0.z = fmaf(w0, h0.z, acc0.z); acc0.w = fmaf(w0, h0.w, acc0.w);
            acc1.x = fmaf(w1, h1.x, acc1.x); acc1.y = fmaf(w1, h1.y, acc1.y);
            acc1.z = fmaf(w1, h1.z, acc1.z); acc1.w = fmaf(w1, h1.w, acc1.w);
        }
    }
#pragma unroll
    for (int o = 16; o; o >>= 1) {
        s0 += __shfl_xor_sync(0xffffffffu, s0, o);
        s1 += __shfl_xor_sync(0xffffffffu, s1, o);
        s2 += __shfl_xor_sync(0xffffffffu, s2, o);
        s3 += __shfl_xor_sync(0xffffffffu, s3, o);
    }

    const float invA = 1.f / (((lane < 16) ? s0 : s1) + 1e-16f);
    const float invB = 1.f / (((lane < 16) ? s2 : s3) + 1e-16f);
    const int hA = (lane < 16) ? 0 : 1;
    const int hB = (lane < 16) ? 2 : 3;
    const int c4 = (lane & 15) * 4;
    const float4 gA = *reinterpret_cast<const float4*>(g_gres + (size_t)n * HO + hA * OUT_F + c4);
    const float4 gB = *reinterpret_cast<const float4*>(g_gres + (size_t)n * HO + hB * OUT_F + c4);
    const float4 bA = *reinterpret_cast<const float4*>(gat_bias + hA * OUT_F + c4);
    const float4 bB = *reinterpret_cast<const float4*>(gat_bias + hB * OUT_F + c4);
    const float cwA = conv_w[hA], cwB = conv_w[hB];

    float4 part;
    part.x = fmaxf(acc0.x * invA + gA.x + bA.x, 0.f) * cwA + fmaxf(acc1.x * invB + gB.x + bB.x, 0.f) * cwB;
    part.y = fmaxf(acc0.y * invA + gA.y + bA.y, 0.f) * cwA + fmaxf(acc1.y * invB + gB.y + bB.y, 0.f) * cwB;
    part.z = fmaxf(acc0.z * invA + gA.z + bA.z, 0.f) * cwA + fmaxf(acc1.z * invB + gB.z + bB.z, 0.f) * cwB;
    part.w = fmaxf(acc0.w * invA + gA.w + bA.w, 0.f) * cwA + fmaxf(acc1.w * invB + gB.w + bB.w, 0.f) * cwB;
    part.x += __shfl_xor_sync(0xffffffffu, part.x, 16);
    part.y += __shfl_xor_sync(0xffffffffu, part.y, 16);
    part.z += __shfl_xor_sync(0xffffffffu, part.z, 16);
    part.w += __shfl_xor_sync(0xffffffffu, part.w, 16);

    __shared__ float shs[8][68];
    __shared__ float shq[8][68];
    if (lane < 16) {
        const float4 y0v = *reinterpret_cast<const float4*>(g_y0 + (size_t)n * OUT_F + c4);
        const float cb = conv_b[0];
        float4 y4;
        y4.x = part.x + cb + y0v.x;
        y4.y = part.y + cb + y0v.y;
        y4.z = part.z + cb + y0v.z;
        y4.w = part.w + cb + y0v.w;
        *reinterpret_cast<float4*>(g_ybuf + (size_t)n * OUT_F + c4) = y4;
        *reinterpret_cast<float4*>(&shs[w][c4]) = y4;
        float4 q = make_float4(y4.x * y4.x, y4.y * y4.y, y4.z * y4.z, y4.w * y4.w);
        *reinterpret_cast<float4*>(&shq[w][c4]) = q;
    }
    if (lane == 0) g_cursor[n] = 0;          // self-clean for next launch
    __syncthreads();

    const int t = threadIdx.x;
    if (t < 64) {
        float sv = 0.f;
#pragma unroll
        for (int r = 0; r < 8; r++) sv += shs[r][t];
        atomicAdd(&g_bnsum[t], sv);
    } else if (t >= 128 && t < 192) {
        int d = t - 128;
        float qv = 0.f;
#pragma unroll
        for (int r = 0; r < 8; r++) qv += shq[r][d];
        atomicAdd(&g_bnsq[d], qv);
    }
}

// ---------------- Kernel 5: BN stats -> scale/shift (+ self-clean) ----------
__global__ void bn_stats_kernel(const float* __restrict__ gamma,
                                const float* __restrict__ beta)
{
    int d = threadIdx.x;
    if (d >= OUT_F) return;
    float mean = g_bnsum[d] / (float)NN;
    float var  = g_bnsq[d] / (float)NN - mean * mean;
    float rstd = rsqrtf(var + BN_EPS);
    float sc = gamma[d] * rstd;
    g_scale[d] = sc;
    g_shift[d] = beta[d] - mean * sc;
    g_bnsum[d] = 0.f;   // self-clean
    g_bnsq[d]  = 0.f;
}

// ---------------- Kernel 6: normalize -> d_out -------------------------------
__global__ void bn_apply_kernel(float* __restrict__ out)
{
    int i = blockIdx.x * blockDim.x + threadIdx.x;
    if (i >= NN * OUT_F) return;
    int d = i & (OUT_F - 1);
    out[i] = g_ybuf[i] * g_scale[d] + g_shift[d];
}

// ---------------- launch -----------------------------------------------------
extern "C" void kernel_launch(void* const* d_in, const int* in_sizes, int n_in,
                              void* d_out, int out_size)
{
    const float* node_feats = (const float*)d_in[0];
    const float* W_fc       = (const float*)d_in[1];
    const float* attn_l     = (const float*)d_in[2];
    const float* attn_r     = (const float*)d_in[3];
    const float* gat_res_w  = (const float*)d_in[4];
    const float* gat_bias   = (const float*)d_in[5];
    const float* conv_w     = (const float*)d_in[6];
    const float* conv_b     = (const float*)d_in[7];
    const float* res_w      = (const float*)d_in[8];
    const float* res_b      = (const float*)d_in[9];
    const float* bn_gamma   = (const float*)d_in[10];
    const float* bn_beta    = (const float*)d_in[11];
    const int*   src        = (const int*)d_in[12];
    const int*   dst        = (const int*)d_in[13];
    float*       out        = (float*)d_out;

    cudaFuncSetAttribute(gemm_kernel, cudaFuncAttributeMaxDynamicSharedMemorySize, SM_TOTAL);

    // edge sort (independent of GEMM output)
    hist_kernel<<<(EE + 255) / 256, 256>>>(dst);
    scan_kernel<<<1, 1024>>>();
    scatter_kernel<<<(EE + 255) / 256, 256>>>(src, dst);

    // three GEMMs on tensor pipe (+ fused el/er epilogue)
    {
        dim3 grid((NN + BMT - 1) / BMT, 9);
        gemm_kernel<<<grid, 256, SM_TOTAL>>>(node_feats, W_fc, gat_res_w, res_w, res_b,
                                             attn_l, attn_r);
    }
    // fused softmax + aggregation + node epilogue + BN partials
    agg_kernel<<<NN / 8, 256>>>(gat_bias, conv_w, conv_b);
    // BN stats
    bn_stats_kernel<<<1, 64>>>(bn_gamma, bn_beta);
    // normalize
    bn_apply_kernel<<<(NN * OUT_F + 255) / 256, 256>>>(out);
}

// round 17
// speedup vs baseline: 1.4100x; 1.0680x over previous
#include <cuda_runtime.h>
#include <cuda_bf16.h>
#include <cstdint>

#define NN    50000
#define EE    800000
#define IN_F  128
#define OUT_F 64
#define NH    4
#define HO    256   // NH*OUT_F
#define NEG_SLOPE 0.2f
#define BN_EPS 1e-5f

#define BMT   64    // M tile
#define PITCH 136   // bf16 elems per smem row (272B: conflict-free, 16B-aligned)
#define NW    576   // total output cols: 256 Wfc | 256 gres | 64 res

// ---------------- scratch (device globals; zero-init at load, self-cleaned) --
__device__ float          g_h     [(size_t)NN * HO];
__device__ float          g_gres  [(size_t)NN * HO];
__device__ float          g_y0    [(size_t)NN * OUT_F];
__device__ float          g_ybuf  [(size_t)NN * OUT_F];
__device__ float          g_el    [NN * NH];
__device__ float          g_er    [NN * NH];
__device__ int            g_deg   [NN];
__device__ int            g_off   [NN];
__device__ int            g_cursor[NN];
__device__ int            g_esrc  [EE];
__device__ float          g_bnsum [OUT_F];
__device__ float          g_bnsq  [OUT_F];
__device__ float          g_scale [OUT_F];
__device__ float          g_shift [OUT_F];
__device__ __nv_bfloat16  g_ah    [(size_t)NN * IN_F];   // A hi (bf16)
__device__ __nv_bfloat16  g_al    [(size_t)NN * IN_F];   // A lo
__device__ __nv_bfloat16  g_wbh   [NW * IN_F];           // W^T hi, [n][k]
__device__ __nv_bfloat16  g_wbl   [NW * IN_F];           // W^T lo

// ---------------- m16n8k16 bf16 MMA (sm_80+ PTX -> HMMA on sm_103) ----------
__device__ __forceinline__ void mma_bf16(float* c, const uint32_t* a,
                                         uint32_t b0, uint32_t b1) {
    asm volatile("mma.sync.aligned.m16n8k16.row.col.f32.bf16.bf16.f32 "
        "{%0,%1,%2,%3}, {%4,%5,%6,%7}, {%8,%9}, {%0,%1,%2,%3};"
        : "+f"(c[0]), "+f"(c[1]), "+f"(c[2]), "+f"(c[3])
        : "r"(a[0]), "r"(a[1]), "r"(a[2]), "r"(a[3]), "r"(b0), "r"(b1));
}

__device__ __forceinline__ void cvt_hilo8(const float* x, uint32_t* hw, uint32_t* lw) {
#pragma unroll
    for (int jp = 0; jp < 4; jp++) {
        __nv_bfloat16 h0 = __float2bfloat16(x[2*jp]);
        __nv_bfloat16 h1 = __float2bfloat16(x[2*jp+1]);
        __nv_bfloat16 l0 = __float2bfloat16(x[2*jp]   - __bfloat162float(h0));
        __nv_bfloat16 l1 = __float2bfloat16(x[2*jp+1] - __bfloat162float(h1));
        hw[jp] = (uint32_t)__bfloat16_as_ushort(h0) | ((uint32_t)__bfloat16_as_ushort(h1) << 16);
        lw[jp] = (uint32_t)__bfloat16_as_ushort(l0) | ((uint32_t)__bfloat16_as_ushort(l1) << 16);
    }
}

// ---------------- Kernel 0a: node_feats fp32 -> bf16 hi/lo -------------------
__global__ void prep_a_kernel(const float* __restrict__ A)
{
    size_t i = (size_t)(blockIdx.x * blockDim.x + threadIdx.x) * 8;
    if (i >= (size_t)NN * IN_F) return;
    const float4* ap = reinterpret_cast<const float4*>(A + i);
    float x[8];
    float4 v0 = ap[0], v1 = ap[1];
    x[0]=v0.x; x[1]=v0.y; x[2]=v0.z; x[3]=v0.w;
    x[4]=v1.x; x[5]=v1.y; x[6]=v1.z; x[7]=v1.w;
    uint32_t hw[4], lw[4];
    cvt_hilo8(x, hw, lw);
    *reinterpret_cast<uint4*>(g_ah + i) = make_uint4(hw[0], hw[1], hw[2], hw[3]);
    *reinterpret_cast<uint4*>(g_al + i) = make_uint4(lw[0], lw[1], lw[2], lw[3]);
}

// ---------------- Kernel 0b: weights -> transposed bf16 hi/lo [n][k] ---------
// n 0-255: Wfc col n | n 256-511: gres col n-256 | n 512-575: res col n-512
__global__ void prep_w_kernel(const float* __restrict__ Wfc,
                              const float* __restrict__ Wgres,
                              const float* __restrict__ Wres)
{
    int i = blockIdx.x * blockDim.x + threadIdx.x;   // NW*16 tasks
    if (i >= NW * 16) return;
    int n  = i >> 4;
    int kg = (i & 15) * 8;
    const float* B; int ldb, col;
    if (n < 256)      { B = Wfc;   ldb = HO;    col = n; }
    else if (n < 512) { B = Wgres; ldb = HO;    col = n - 256; }
    else              { B = Wres;  ldb = OUT_F; col = n - 512; }
    float x[8];
#pragma unroll
    for (int j = 0; j < 8; j++) x[j] = B[(size_t)(kg + j) * ldb + col];
    uint32_t hw[4], lw[4];
    cvt_hilo8(x, hw, lw);
    *reinterpret_cast<uint4*>(g_wbh + n * IN_F + kg) = make_uint4(hw[0], hw[1], hw[2], hw[3]);
    *reinterpret_cast<uint4*>(g_wbl + n * IN_F + kg) = make_uint4(lw[0], lw[1], lw[2], lw[3]);
}

// smem layout (bf16 elems): AH | AL | BH | BL, then float ELP[4][64], ERP[4][64]
#define SM_TOTAL (4 * BMT * PITCH * 2 + 2 * 4 * BMT * 4)

// ---------------- Kernel 1: tensor-core GEMM (pre-converted bf16 hi/lo) ------
// Block tile 64(M) x 64(N), K=128. 256 threads = 8 warps: w&1 = m-half,
// w>>1 = n-quarter. grid = (ceil(NN/64), 9): ct 0-3 Wfc head ct | 4-7 gres | 8 res
__global__ void __launch_bounds__(256, 2)
gemm_kernel(const float* __restrict__ res_b,
            const float* __restrict__ attn_l,
            const float* __restrict__ attn_r)
{
    extern __shared__ char smem[];
    __nv_bfloat16* AH = reinterpret_cast<__nv_bfloat16*>(smem);
    __nv_bfloat16* AL = AH + BMT * PITCH;
    __nv_bfloat16* BH = AL + BMT * PITCH;
    __nv_bfloat16* BL = BH + BMT * PITCH;
    float* ELP = reinterpret_cast<float*>(BL + BMT * PITCH);   // [4][64]
    float* ERP = ELP + 4 * BMT;

    const int ct = blockIdx.y;
    int nbase, colbase, mode;
    if (ct < 4)      { nbase = ct * 64;              colbase = ct * 64;       mode = 0; }
    else if (ct < 8) { nbase = 256 + (ct - 4) * 64;  colbase = (ct - 4) * 64; mode = 1; }
    else             { nbase = 512;                  colbase = 0;             mode = 2; }

    const int t    = threadIdx.x;
    const int row0 = blockIdx.x * BMT;

    // ---- fill A tiles (plain 16B copies of pre-converted bf16) --------------
    for (int i = t; i < BMT * 16; i += 256) {
        int m  = i >> 4;
        int kg = (i & 15) * 8;
        int grow = row0 + m;
        uint4 vh, vl;
        if (grow < NN) {
            vh = *reinterpret_cast<const uint4*>(g_ah + (size_t)grow * IN_F + kg);
            vl = *reinterpret_cast<const uint4*>(g_al + (size_t)grow * IN_F + kg);
        } else {
            vh = make_uint4(0u, 0u, 0u, 0u); vl = vh;
        }
        *reinterpret_cast<uint4*>(AH + m * PITCH + kg) = vh;
        *reinterpret_cast<uint4*>(AL + m * PITCH + kg) = vl;
    }
    // ---- fill B tiles --------------------------------------------------------
    for (int i = t; i < 64 * 16; i += 256) {
        int n  = i >> 4;
        int kg = (i & 15) * 8;
        *reinterpret_cast<uint4*>(BH + n * PITCH + kg) =
            *reinterpret_cast<const uint4*>(g_wbh + (nbase + n) * IN_F + kg);
        *reinterpret_cast<uint4*>(BL + n * PITCH + kg) =
            *reinterpret_cast<const uint4*>(g_wbl + (nbase + n) * IN_F + kg);
    }
    __syncthreads();

    // ---- warp tiling ---------------------------------------------------------
    const int lane = t & 31;
    const int w    = t >> 5;
    const int m0   = (w & 1) * 32;
    const int n0   = (w >> 1) * 16;
    const int g    = lane >> 2;
    const int tt   = lane & 3;

    float acc[2][2][4];
#pragma unroll
    for (int mi = 0; mi < 2; mi++)
#pragma unroll
        for (int nj = 0; nj < 2; nj++)
#pragma unroll
            for (int q = 0; q < 4; q++) acc[mi][nj][q] = 0.f;

    // 3 passes: AhBh, AhBl, AlBh
#pragma unroll
    for (int pass = 0; pass < 3; pass++) {
        const __nv_bfloat16* Asm = (pass == 2) ? AL : AH;
        const __nv_bfloat16* Bsm = (pass == 1) ? BL : BH;
#pragma unroll
        for (int ks = 0; ks < 8; ks++) {
            const int k0 = ks * 16;
            uint32_t a[2][4];
#pragma unroll
            for (int mi = 0; mi < 2; mi++) {
                const __nv_bfloat16* p = Asm + (m0 + mi * 16 + g) * PITCH + k0 + tt * 2;
                a[mi][0] = *reinterpret_cast<const uint32_t*>(p);
                a[mi][1] = *reinterpret_cast<const uint32_t*>(p + 8 * PITCH);
                a[mi][2] = *reinterpret_cast<const uint32_t*>(p + 8);
                a[mi][3] = *reinterpret_cast<const uint32_t*>(p + 8 * PITCH + 8);
            }
#pragma unroll
            for (int nj = 0; nj < 2; nj++) {
                const __nv_bfloat16* q = Bsm + (n0 + nj * 8 + g) * PITCH + k0 + tt * 2;
                uint32_t b0 = *reinterpret_cast<const uint32_t*>(q);
                uint32_t b1 = *reinterpret_cast<const uint32_t*>(q + 8);
                mma_bf16(acc[0][nj], a[0], b0, b1);
                mma_bf16(acc[1][nj], a[1], b0, b1);
            }
        }
    }

    // ---- store outputs -------------------------------------------------------
#pragma unroll
    for (int mi = 0; mi < 2; mi++) {
#pragma unroll
        for (int nj = 0; nj < 2; nj++) {
            int lrow = m0 + mi * 16 + g;
            int col  = colbase + n0 + nj * 8 + tt * 2;
            int r0g  = row0 + lrow;
            int r1g  = r0g + 8;
            float2 v0 = make_float2(acc[mi][nj][0], acc[mi][nj][1]);
            float2 v1 = make_float2(acc[mi][nj][2], acc[mi][nj][3]);
            if (mode == 0) {
                if (r0g < NN) *reinterpret_cast<float2*>(g_h + (size_t)r0g * HO + col) = v0;
                if (r1g < NN) *reinterpret_cast<float2*>(g_h + (size_t)r1g * HO + col) = v1;
            } else if (mode == 1) {
                if (r0g < NN) *reinterpret_cast<float2*>(g_gres + (size_t)r0g * HO + col) = v0;
                if (r1g < NN) *reinterpret_cast<float2*>(g_gres + (size_t)r1g * HO + col) = v1;
            } else {
                float rb0 = res_b[col], rb1 = res_b[col + 1];
                if (r0g < NN)
                    *reinterpret_cast<float2*>(g_y0 + (size_t)r0g * OUT_F + col) =
                        make_float2(fmaxf(v0.x + rb0, 0.f), fmaxf(v0.y + rb1, 0.f));
                if (r1g < NN)
                    *reinterpret_cast<float2*>(g_y0 + (size_t)r1g * OUT_F + col) =
                        make_float2(fmaxf(v1.x + rb0, 0.f), fmaxf(v1.y + rb1, 0.f));
            }
        }
    }

    // ---- fused el/er (mode 0): per-row dot with attn vectors -----------------
    if (mode == 0) {
        const int head = ct;
#pragma unroll
        for (int mi = 0; mi < 2; mi++) {
#pragma unroll
            for (int hh = 0; hh < 2; hh++) {
                int lrow = m0 + mi * 16 + g + hh * 8;
                float el = 0.f, er = 0.f;
#pragma unroll
                for (int nj = 0; nj < 2; nj++) {
                    int col = n0 + nj * 8 + tt * 2;   // head-local
                    float c0 = acc[mi][nj][hh * 2];
                    float c1 = acc[mi][nj][hh * 2 + 1];
                    el += c0 * attn_l[head * OUT_F + col] + c1 * attn_l[head * OUT_F + col + 1];
                    er += c0 * attn_r[head * OUT_F + col] + c1 * attn_r[head * OUT_F + col + 1];
                }
                el += __shfl_xor_sync(0xffffffffu, el, 1);
                el += __shfl_xor_sync(0xffffffffu, el, 2);
                er += __shfl_xor_sync(0xffffffffu, er, 1);
                er += __shfl_xor_sync(0xffffffffu, er, 2);
                if (tt == 0) {
                    ELP[(w >> 1) * BMT + lrow] = el;
                    ERP[(w >> 1) * BMT + lrow] = er;
                }
            }
        }
    }
    __syncthreads();
    if (mode == 0 && t < BMT) {
        int grow = row0 + t;
        if (grow < NN) {
            float el = ELP[t] + ELP[BMT + t] + ELP[2 * BMT + t] + ELP[3 * BMT + t];
            float er = ERP[t] + ERP[BMT + t] + ERP[2 * BMT + t] + ERP[3 * BMT + t];
            g_el[grow * NH + ct] = el;
            g_er[grow * NH + ct] = er;
        }
    }
}

// ---------------- Kernel 3a: degree histogram --------------------------------
__global__ void hist_kernel(const int* __restrict__ dst)
{
    int e = blockIdx.x * blockDim.x + threadIdx.x;
    if (e >= EE) return;
    atomicAdd(&g_deg[dst[e]], 1);
}

// ---------------- Kernel 3b: exclusive scan (1 block) + zero g_deg ----------
__global__ void scan_kernel()
{
    const int tid = threadIdx.x;   // 1024 threads
    __shared__ int wsum[32];
    __shared__ int s_carry;
    if (tid == 0) s_carry = 0;
    __syncthreads();
    for (int base = 0; base < NN; base += 1024) {
        int i = base + tid;
        int v = (i < NN) ? g_deg[i] : 0;
        if (i < NN) g_deg[i] = 0;            // self-clean
        int incl = v;
#pragma unroll
        for (int o = 1; o < 32; o <<= 1) {
            int t = __shfl_up_sync(0xffffffffu, incl, o);
            if ((tid & 31) >= o) incl += t;
        }
        if ((tid & 31) == 31) wsum[tid >> 5] = incl;
        __syncthreads();
        if (tid < 32) {
            int w = wsum[tid];
            int wi = w;
#pragma unroll
            for (int o = 1; o < 32; o <<= 1) {
                int t = __shfl_up_sync(0xffffffffu, wi, o);
                if (tid >= o) wi += t;
            }
            wsum[tid] = wi - w;              // exclusive warp offset
        }
        __syncthreads();
        incl += wsum[tid >> 5];
        int carry = s_carry;
        if (i < NN) g_off[i] = carry + incl - v;
        __syncthreads();
        if (tid == 1023) s_carry = carry + incl;
        __syncthreads();
    }
}

// ---------------- Kernel 3c: scatter src into dst-sorted order ---------------
__global__ void scatter_kernel(const int* __restrict__ src,
                               const int* __restrict__ dst)
{
    int e = blockIdx.x * blockDim.x + threadIdx.x;
    if (e >= EE) return;
    int d = dst[e];
    int p = g_off[d] + atomicAdd(&g_cursor[d], 1);
    g_esrc[p] = src[e];
}

// ---------------- Kernel 4: fused per-dst softmax + aggregation + epilogue --
__global__ void agg_kernel(const float* __restrict__ gat_bias,
                           const float* __restrict__ conv_w,
                           const float* __restrict__ conv_b)
{
    const int lane = threadIdx.x & 31;
    const int w    = threadIdx.x >> 5;      // 0..7
    const int n    = blockIdx.x * 8 + w;

    const int off = g_off[n];
    const int deg = g_cursor[n];

    const float4 er4 = *reinterpret_cast<const float4*>(g_er + n * 4);

    float m0 = -1e30f, m1 = -1e30f, m2 = -1e30f, m3 = -1e30f;
    for (int base = 0; base < deg; base += 32) {
        int e = base + lane;
        int s = (e < deg) ? g_esrc[off + e] : 0;
        float4 elv = *reinterpret_cast<const float4*>(g_el + s * 4);
        float l0 = elv.x + er4.x; l0 = (l0 >= 0.f) ? l0 : NEG_SLOPE * l0;
        float l1 = elv.y + er4.y; l1 = (l1 >= 0.f) ? l1 : NEG_SLOPE * l1;
        float l2 = elv.z + er4.z; l2 = (l2 >= 0.f) ? l2 : NEG_SLOPE * l2;
        float l3 = elv.w + er4.w; l3 = (l3 >= 0.f) ? l3 : NEG_SLOPE * l3;
        if (e < deg) {
            m0 = fmaxf(m0, l0); m1 = fmaxf(m1, l1);
            m2 = fmaxf(m2, l2); m3 = fmaxf(m3, l3);
        }
    }
#pragma unroll
    for (int o = 16; o; o >>= 1) {
        m0 = fmaxf(m0, __shfl_xor_sync(0xffffffffu, m0, o));
        m1 = fmaxf(m1, __shfl_xor_sync(0xffffffffu, m1, o));
        m2 = fmaxf(m2, __shfl_xor_sync(0xffffffffu, m2, o));
        m3 = fmaxf(m3, __shfl_xor_sync(0xffffffffu, m3, o));
    }

    float s0 = 0.f, s1 = 0.f, s2 = 0.f, s3 = 0.f;
    float4 acc0 = make_float4(0.f, 0.f, 0.f, 0.f);
    float4 acc1 = make_float4(0.f, 0.f, 0.f, 0.f);
    for (int base = 0; base < deg; base += 32) {
        int cnt = min(32, deg - base);
        int e = base + lane;
        int sidx = (e < deg) ? g_esrc[off + e] : 0;
        float4 elv = *reinterpret_cast<const float4*>(g_el + sidx * 4);
        float l0 = elv.x + er4.x; l0 = (l0 >= 0.f) ? l0 : NEG_SLOPE * l0;
        float l1 = elv.y + er4.y; l1 = (l1 >= 0.f) ? l1 : NEG_SLOPE * l1;
        float l2 = elv.z + er4.z; l2 = (l2 >= 0.f) ? l2 : NEG_SLOPE * l2;
        float l3 = elv.w + er4.w; l3 = (l3 >= 0.f) ? l3 : NEG_SLOPE * l3;
        float a0 = (e < deg) ? __expf(l0 - m0) : 0.f;
        float a1 = (e < deg) ? __expf(l1 - m1) : 0.f;
        float a2 = (e < deg) ? __expf(l2 - m2) : 0.f;
        float a3 = (e < deg) ? __expf(l3 - m3) : 0.f;
        s0 += a0; s1 += a1; s2 += a2; s3 += a3;

        for (int ee = 0; ee < cnt; ee++) {
            int   sv = __shfl_sync(0xffffffffu, sidx, ee);
            float b0 = __shfl_sync(0xffffffffu, a0, ee);
            float b1 = __shfl_sync(0xffffffffu, a1, ee);
            float b2 = __shfl_sync(0xffffffffu, a2, ee);
            float b3 = __shfl_sync(0xffffffffu, a3, ee);
            float w0 = (lane < 16) ? b0 : b1;
            float w1 = (lane < 16) ? b2 : b3;
            const float4* hrow = reinterpret_cast<const float4*>(g_h + (size_t)sv * HO);
            float4 h0 = hrow[lane];
            float4 h1 = hrow[lane + 32];
            acc0.x = fmaf(w0, h0.x, acc0.x); acc0.y = fmaf(w0, h0.y, acc0.y);
            acc0.z = fmaf(w0, h0.z, acc0.z); acc0.w = fmaf(w0, h0.w, acc0.w);
            acc1.x = fmaf(w1, h1.x, acc1.x); acc1.y = fmaf(w1, h1.y, acc1.y);
            acc1.z = fmaf(w1, h1.z, acc1.z); acc1.w = fmaf(w1, h1.w, acc1.w);
        }
    }
#pragma unroll
    for (int o = 16; o; o >>= 1) {
        s0 += __shfl_xor_sync(0xffffffffu, s0, o);
        s1 += __shfl_xor_sync(0xffffffffu, s1, o);
        s2 += __shfl_xor_sync(0xffffffffu, s2, o);
        s3 += __shfl_xor_sync(0xffffffffu, s3, o);
    }

    const float invA = 1.f / (((lane < 16) ? s0 : s1) + 1e-16f);
    const float invB = 1.f / (((lane < 16) ? s2 : s3) + 1e-16f);
    const int hA = (lane < 16) ? 0 : 1;
    const int hB = (lane < 16) ? 2 : 3;
    const int c4 = (lane & 15) * 4;
    const float4 gA = *reinterpret_cast<const float4*>(g_gres + (size_t)n * HO + hA * OUT_F + c4);
    const float4 gB = *reinterpret_cast<const float4*>(g_gres + (size_t)n * HO + hB * OUT_F + c4);
    const float4 bA = *reinterpret_cast<const float4*>(gat_bias + hA * OUT_F + c4);
    const float4 bB = *reinterpret_cast<const float4*>(gat_bias + hB * OUT_F + c4);
    const float cwA = conv_w[hA], cwB = conv_w[hB];

    float4 part;
    part.x = fmaxf(acc0.x * invA + gA.x + bA.x, 0.f) * cwA + fmaxf(acc1.x * invB + gB.x + bB.x, 0.f) * cwB;
    part.y = fmaxf(acc0.y * invA + gA.y + bA.y, 0.f) * cwA + fmaxf(acc1.y * invB + gB.y + bB.y, 0.f) * cwB;
    part.z = fmaxf(acc0.z * invA + gA.z + bA.z, 0.f) * cwA + fmaxf(acc1.z * invB + gB.z + bB.z, 0.f) * cwB;
    part.w = fmaxf(acc0.w * invA + gA.w + bA.w, 0.f) * cwA + fmaxf(acc1.w * invB + gB.w + bB.w, 0.f) * cwB;
    part.x += __shfl_xor_sync(0xffffffffu, part.x, 16);
    part.y += __shfl_xor_sync(0xffffffffu, part.y, 16);
    part.z += __shfl_xor_sync(0xffffffffu, part.z, 16);
    part.w += __shfl_xor_sync(0xffffffffu, part.w, 16);

    __shared__ float shs[8][68];
    __shared__ float shq[8][68];
    if (lane < 16) {
        const float4 y0v = *reinterpret_cast<const float4*>(g_y0 + (size_t)n * OUT_F + c4);
        const float cb = conv_b[0];
        float4 y4;
        y4.x = part.x + cb + y0v.x;
        y4.y = part.y + cb + y0v.y;
        y4.z = part.z + cb + y0v.z;
        y4.w = part.w + cb + y0v.w;
        *reinterpret_cast<float4*>(g_ybuf + (size_t)n * OUT_F + c4) = y4;
        *reinterpret_cast<float4*>(&shs[w][c4]) = y4;
        float4 q = make_float4(y4.x * y4.x, y4.y * y4.y, y4.z * y4.z, y4.w * y4.w);
        *reinterpret_cast<float4*>(&shq[w][c4]) = q;
    }
    if (lane == 0) g_cursor[n] = 0;          // self-clean for next launch
    __syncthreads();

    const int t = threadIdx.x;
    if (t < 64) {
        float sv = 0.f;
#pragma unroll
        for (int r = 0; r < 8; r++) sv += shs[r][t];
        atomicAdd(&g_bnsum[t], sv);
    } else if (t >= 128 && t < 192) {
        int d = t - 128;
        float qv = 0.f;
#pragma unroll
        for (int r = 0; r < 8; r++) qv += shq[r][d];
        atomicAdd(&g_bnsq[d], qv);
    }
}

// ---------------- Kernel 5: BN stats -> scale/shift (+ self-clean) ----------
__global__ void bn_stats_kernel(const float* __restrict__ gamma,
                                const float* __restrict__ beta)
{
    int d = threadIdx.x;
    if (d >= OUT_F) return;
    float mean = g_bnsum[d] / (float)NN;
    float var  = g_bnsq[d] / (float)NN - mean * mean;
    float rstd = rsqrtf(var + BN_EPS);
    float sc = gamma[d] * rstd;
    g_scale[d] = sc;
    g_shift[d] = beta[d] - mean * sc;
    g_bnsum[d] = 0.f;   // self-clean
    g_bnsq[d]  = 0.f;
}

// ---------------- Kernel 6: normalize -> d_out -------------------------------
__global__ void bn_apply_kernel(float* __restrict__ out)
{
    int i = blockIdx.x * blockDim.x + threadIdx.x;
    if (i >= NN * OUT_F) return;
    int d = i & (OUT_F - 1);
    out[i] = g_ybuf[i] * g_scale[d] + g_shift[d];
}

// ---------------- launch -----------------------------------------------------
extern "C" void kernel_launch(void* const* d_in, const int* in_sizes, int n_in,
                              void* d_out, int out_size)
{
    const float* node_feats = (const float*)d_in[0];
    const float* W_fc       = (const float*)d_in[1];
    const float* attn_l     = (const float*)d_in[2];
    const float* attn_r     = (const float*)d_in[3];
    const float* gat_res_w  = (const float*)d_in[4];
    const float* gat_bias   = (const float*)d_in[5];
    const float* conv_w     = (const float*)d_in[6];
    const float* conv_b     = (const float*)d_in[7];
    const float* res_w      = (const float*)d_in[8];
    const float* res_b      = (const float*)d_in[9];
    const float* bn_gamma   = (const float*)d_in[10];
    const float* bn_beta    = (const float*)d_in[11];
    const int*   src        = (const int*)d_in[12];
    const int*   dst        = (const int*)d_in[13];
    float*       out        = (float*)d_out;

    cudaFuncSetAttribute(gemm_kernel, cudaFuncAttributeMaxDynamicSharedMemorySize, SM_TOTAL);

    // prep: fp32 -> bf16 hi/lo (A and W)
    prep_a_kernel<<<(NN * IN_F / 8 + 255) / 256, 256>>>(node_feats);
    prep_w_kernel<<<(NW * 16 + 255) / 256, 256>>>(W_fc, gat_res_w, res_w);

    // edge sort (independent of GEMM output)
    hist_kernel<<<(EE + 255) / 256, 256>>>(dst);
    scan_kernel<<<1, 1024>>>();
    scatter_kernel<<<(EE + 255) / 256, 256>>>(src, dst);

    // three GEMMs on tensor pipe (+ fused el/er epilogue)
    {
        dim3 grid((NN + BMT - 1) / BMT, 9);
        gemm_kernel<<<grid, 256, SM_TOTAL>>>(res_b, attn_l, attn_r);
    }
    // fused softmax + aggregation + node epilogue + BN partials
    agg_kernel<<<NN / 8, 256>>>(gat_bias, conv_w, conv_b);
    // BN stats
    bn_stats_kernel<<<1, 64>>>(bn_gamma, bn_beta);
    // normalize
    bn_apply_kernel<<<(NN * OUT_F + 255) / 256, 256>>>(out);
}